// round 2
// baseline (speedup 1.0000x reference)
#include <cuda_runtime.h>
#include <cstdint>
#include <cstddef>

#define Mdim 128
#define Ndim 64
#define Edim 32
#define Sdim 512
#define Bdim 8192

// ---------------- scratch (no allocation allowed) ----------------
__device__ float g_zc[Bdim * Ndim];   // z_cur transposed: [b*64 + i]
__device__ float g_w [Bdim * Edim];   // expert weights:   [b*32 + e]

// ---------------- Kernel 1: z_cur = D @ z + sigma_g * noise (transposed out) ----------------
__global__ void k_zc(const float* __restrict__ z, const float* __restrict__ noise,
                     const float* __restrict__ Dm, const float* __restrict__ sigma_g)
{
    int b = blockIdx.x * blockDim.x + threadIdx.x;   // coalesced over b
    int i = blockIdx.y;                              // 0..63
    float acc = sigma_g[i] * noise[(size_t)i * Bdim + b];
    const float* drow = Dm + i * Mdim;
    #pragma unroll 8
    for (int m = 0; m < Mdim; ++m)
        acc = fmaf(drow[m], z[(size_t)m * Bdim + b], acc);
    g_zc[(size_t)b * Ndim + i] = acc;
}

// ---------------- Kernel 2: streaming online-softmax attention + conv-emb + MLP + expert softmax ----------------
#define K2_WARPS 8
#define CHUNK 8

struct OnlineState {
    float mrun, denom, pprev;
    float c0x, c0y, c1x, c1y;
};

__device__ __forceinline__ void row_proc(const float2 v, float zcx, float zcy,
                                         float invT1, OnlineState& st)
{
    float dd = fabsf(v.x - zcx) + fabsf(v.y - zcy);
    dd += __shfl_xor_sync(0xffffffffu, dd, 16);
    dd += __shfl_xor_sync(0xffffffffu, dd, 8);
    dd += __shfl_xor_sync(0xffffffffu, dd, 4);
    dd += __shfl_xor_sync(0xffffffffu, dd, 2);
    dd += __shfl_xor_sync(0xffffffffu, dd, 1);
    float logit = -dd * invT1;
    if (logit > st.mrun) {
        float s = __expf(st.mrun - logit);
        st.denom *= s; st.c0x *= s; st.c0y *= s; st.c1x *= s; st.c1y *= s; st.pprev *= s;
        st.mrun = logit;
    }
    float pw = __expf(logit - st.mrun);
    st.denom += pw;
    st.c0x = fmaf(pw, v.x, st.c0x);       st.c0y = fmaf(pw, v.y, st.c0y);
    st.c1x = fmaf(st.pprev, v.x, st.c1x); st.c1y = fmaf(st.pprev, v.y, st.c1y);
    st.pprev = pw;
}

__device__ __forceinline__ void load_chunk(float2* buf, const float2* p, size_t TSTEP, int cidx)
{
    const float2* q = p + (size_t)cidx * (size_t)CHUNK * TSTEP;
    #pragma unroll
    for (int r = 0; r < CHUNK; ++r) buf[r] = __ldcs(q + (size_t)r * TSTEP);
}

__device__ __forceinline__ void proc_chunk(const float2* buf, float zcx, float zcy,
                                           float invT1, OnlineState& st)
{
    #pragma unroll
    for (int r = 0; r < CHUNK; ++r) row_proc(buf[r], zcx, zcy, invT1, st);
}

__global__ __launch_bounds__(256, 4)
void k_attn(const float* __restrict__ ctx, const float* __restrict__ z,
            const float* __restrict__ conv_w, const float* __restrict__ conv_b,
            const float* __restrict__ temp1,
            const float* __restrict__ W1, const float* __restrict__ b1,
            const float* __restrict__ W2, const float* __restrict__ b2,
            const float* __restrict__ temp2)
{
    __shared__ float W1s[192 * 32];          // transposed [j][e]
    __shared__ float W2s[32 * 32];           // transposed [j][e]
    __shared__ float scomb[K2_WARPS][194];   // per-warp c0|c1 then emb|z (192 used)

    int tid = threadIdx.x;
    for (int t = tid; t < 192 * 32; t += 256) {
        int e = t / 192, j = t % 192;
        W1s[j * 32 + e] = W1[t];
    }
    for (int t = tid; t < 32 * 32; t += 256) {
        int e = t / 32, j = t % 32;
        W2s[j * 32 + e] = W2[t];
    }
    __syncthreads();

    int warp = tid >> 5, lane = tid & 31;
    int b = blockIdx.x * K2_WARPS + warp;

    float invT1 = 1.0f / fabsf(temp1[0]);
    float invT2 = 1.0f / fabsf(temp2[0]);

    float zcx = g_zc[(size_t)b * Ndim + 2 * lane];
    float zcy = g_zc[(size_t)b * Ndim + 2 * lane + 1];

    const float2* p = reinterpret_cast<const float2*>(ctx) + (size_t)b * (Ndim / 2) + lane;
    const size_t TSTEP = (size_t)Bdim * (Ndim / 2);  // float2 per seq step

    OnlineState st;
    st.mrun = -1e30f; st.denom = 0.f; st.pprev = 0.f;
    st.c0x = 0.f; st.c0y = 0.f; st.c1x = 0.f; st.c1y = 0.f;
    float2 buf0[CHUNK], buf1[CHUNK];

    load_chunk(buf0, p, TSTEP, 0);
    for (int cc = 0; cc < 62; cc += 2) {
        load_chunk(buf1, p, TSTEP, cc + 1);
        proc_chunk(buf0, zcx, zcy, invT1, st);
        load_chunk(buf0, p, TSTEP, cc + 2);
        proc_chunk(buf1, zcx, zcy, invT1, st);
    }
    load_chunk(buf1, p, TSTEP, 63);
    proc_chunk(buf0, zcx, zcy, invT1, st);   // chunk 62 (rows 496..503)
    // chunk 63: rows 504..510 normal, row 511 only feeds c1 (shifted tap)
    #pragma unroll
    for (int r = 0; r < CHUNK - 1; ++r) row_proc(buf1[r], zcx, zcy, invT1, st);
    {
        float2 v = buf1[CHUNK - 1];
        st.c1x = fmaf(st.pprev, v.x, st.c1x);
        st.c1y = fmaf(st.pprev, v.y, st.c1y);
    }

    float rinv = 1.0f / st.denom;
    float* sc = scomb[warp];
    sc[2 * lane]      = st.c0x * rinv;  sc[2 * lane + 1]      = st.c0y * rinv;
    sc[64 + 2 * lane] = st.c1x * rinv;  sc[64 + 2 * lane + 1] = st.c1y * rinv;
    __syncwarp();

    // emb[o] = conv_b[o] + sum_i cw0[o,i]*c0[i] + cw1[o,i]*c1[i]
    int o0 = 2 * lane, o1 = 2 * lane + 1;
    float e0 = conv_b[o0], e1 = conv_b[o1];
    const float* cwA = conv_w + (size_t)o0 * 128;   // conv_w[o][i][tap], stride 2 over i
    const float* cwB = conv_w + (size_t)o1 * 128;
    #pragma unroll 8
    for (int i = 0; i < 64; ++i) {
        float a = sc[i], c = sc[64 + i];
        e0 = fmaf(__ldg(cwA + 2 * i), a, e0);
        e0 = fmaf(__ldg(cwA + 2 * i + 1), c, e0);
        e1 = fmaf(__ldg(cwB + 2 * i), a, e1);
        e1 = fmaf(__ldg(cwB + 2 * i + 1), c, e1);
    }
    __syncwarp();
    sc[o0] = e0; sc[o1] = e1;                      // combined[0..63] = emb
    #pragma unroll
    for (int k = 0; k < 4; ++k) {
        int j = lane * 4 + k;
        sc[64 + j] = __ldg(z + (size_t)j * Bdim + b);  // combined[64..191] = z[:,b]
    }
    __syncwarp();

    // hidden[e] = relu(W1[e,:] . combined + b1[e]), lane == e
    float hs = b1[lane];
    #pragma unroll 8
    for (int j = 0; j < 192; ++j)
        hs = fmaf(W1s[j * 32 + lane], sc[j], hs);
    hs = fmaxf(hs, 0.f);

    float o2 = b2[lane];
    #pragma unroll
    for (int j = 0; j < 32; ++j)
        o2 = fmaf(W2s[j * 32 + lane], __shfl_sync(0xffffffffu, hs, j), o2);

    // expert softmax over lanes
    float lg = -o2 * invT2;
    float mx = lg;
    mx = fmaxf(mx, __shfl_xor_sync(0xffffffffu, mx, 16));
    mx = fmaxf(mx, __shfl_xor_sync(0xffffffffu, mx, 8));
    mx = fmaxf(mx, __shfl_xor_sync(0xffffffffu, mx, 4));
    mx = fmaxf(mx, __shfl_xor_sync(0xffffffffu, mx, 2));
    mx = fmaxf(mx, __shfl_xor_sync(0xffffffffu, mx, 1));
    float pw2 = __expf(lg - mx);
    float sm2 = pw2;
    sm2 += __shfl_xor_sync(0xffffffffu, sm2, 16);
    sm2 += __shfl_xor_sync(0xffffffffu, sm2, 8);
    sm2 += __shfl_xor_sync(0xffffffffu, sm2, 4);
    sm2 += __shfl_xor_sync(0xffffffffu, sm2, 2);
    sm2 += __shfl_xor_sync(0xffffffffu, sm2, 1);
    g_w[(size_t)b * 32 + lane] = pw2 / sm2;
}

// ---------------- Kernel 3: out[m,b] = sum_{e,k} Wx[e,m,k]*w[e,b]*zcat[k,b] + z*.(A^T w) + h^T w ----------------
#define K3_BT 64
#define K3_MT 64

__global__ __launch_bounds__(256, 2)
void k_mix(const float* __restrict__ z, const float* __restrict__ Wx,
           const float* __restrict__ Amat, const float* __restrict__ hmat,
           float* __restrict__ out)
{
    __shared__ float Ws[32][K3_MT + 4];
    __shared__ float Vs[32][K3_BT + 4];
    __shared__ float w_s[32][K3_BT + 1];

    int tid = threadIdx.x;
    int b0 = blockIdx.x * K3_BT;
    int m0 = blockIdx.y * K3_MT;
    int tx = tid & 15, ty = tid >> 4;

    // stage expert-weight tile: w_s[e][b]
    #pragma unroll
    for (int r = 0; r < 8; ++r) {
        int idx = tid + r * 256;
        int bb = idx >> 5, e = idx & 31;
        w_s[e][bb] = g_w[(size_t)(b0 + bb) * 32 + e];
    }

    float acc[4][4]  = {};
    float accA[4][4] = {};

    for (int c = 0; c < 128; ++c) {
        int e = c >> 2, k0 = (c & 3) << 5;
        __syncthreads();
        // Ws[kk][m] = Wx[e, m0+m, k0+kk]  (transpose on store)
        const float* wxb = Wx + (size_t)e * (Mdim * Mdim) + (size_t)m0 * Mdim + k0;
        #pragma unroll
        for (int r = 0; r < 2; ++r) {
            int q = tid + r * 256;               // 0..511 float4s
            int mm = q >> 3, kq = q & 7;
            float4 v4 = *reinterpret_cast<const float4*>(wxb + (size_t)mm * Mdim + kq * 4);
            Ws[kq * 4 + 0][mm] = v4.x;
            Ws[kq * 4 + 1][mm] = v4.y;
            Ws[kq * 4 + 2][mm] = v4.z;
            Ws[kq * 4 + 3][mm] = v4.w;
        }
        // Vs[kk][b] = w[e,b] * zcat[k0+kk, b]
        #pragma unroll
        for (int r = 0; r < 8; ++r) {
            int idx = tid + r * 256;             // 0..2047
            int kk = idx >> 6, bb = idx & 63;
            int kg = k0 + kk;
            float zv = z[(size_t)kg * Bdim + b0 + bb];
            if (kg >= Mdim - 2) zv = fmaxf(zv, 0.f);   // relu on last P=2 rows
            Vs[kk][bb] = zv * w_s[e][bb];
        }
        __syncthreads();
        #pragma unroll
        for (int kk = 0; kk < 32; ++kk) {
            float4 v  = *reinterpret_cast<const float4*>(&Vs[kk][tx * 4]);
            float4 wv = *reinterpret_cast<const float4*>(&Ws[kk][ty * 4]);
            float vv[4]  = {v.x, v.y, v.z, v.w};
            float wvv[4] = {wv.x, wv.y, wv.z, wv.w};
            #pragma unroll
            for (int i = 0; i < 4; ++i)
                #pragma unroll
                for (int j = 0; j < 4; ++j)
                    acc[i][j] = fmaf(wvv[i], vv[j], acc[i][j]);
        }
    }

    // h chunk: acc += h[e,m]*w[e,b]
    __syncthreads();
    #pragma unroll
    for (int r = 0; r < 8; ++r) {
        int idx = tid + r * 256;
        int e = idx >> 6, xx = idx & 63;
        Ws[e][xx] = hmat[(size_t)e * Mdim + m0 + xx];
        Vs[e][xx] = w_s[e][xx];
    }
    __syncthreads();
    #pragma unroll
    for (int kk = 0; kk < 32; ++kk) {
        float4 v  = *reinterpret_cast<const float4*>(&Vs[kk][tx * 4]);
        float4 wv = *reinterpret_cast<const float4*>(&Ws[kk][ty * 4]);
        float vv[4]  = {v.x, v.y, v.z, v.w};
        float wvv[4] = {wv.x, wv.y, wv.z, wv.w};
        #pragma unroll
        for (int i = 0; i < 4; ++i)
            #pragma unroll
            for (int j = 0; j < 4; ++j)
                acc[i][j] = fmaf(wvv[i], vv[j], acc[i][j]);
    }

    // A chunk: accA = sum_e A[e,m]*w[e,b]  (Vs already holds w)
    __syncthreads();
    #pragma unroll
    for (int r = 0; r < 8; ++r) {
        int idx = tid + r * 256;
        int e = idx >> 6, xx = idx & 63;
        Ws[e][xx] = Amat[(size_t)e * Mdim + m0 + xx];
    }
    __syncthreads();
    #pragma unroll
    for (int kk = 0; kk < 32; ++kk) {
        float4 v  = *reinterpret_cast<const float4*>(&Vs[kk][tx * 4]);
        float4 wv = *reinterpret_cast<const float4*>(&Ws[kk][ty * 4]);
        float vv[4]  = {v.x, v.y, v.z, v.w};
        float wvv[4] = {wv.x, wv.y, wv.z, wv.w};
        #pragma unroll
        for (int i = 0; i < 4; ++i)
            #pragma unroll
            for (int j = 0; j < 4; ++j)
                accA[i][j] = fmaf(wvv[i], vv[j], accA[i][j]);
    }

    // epilogue: out = acc + z .* accA
    #pragma unroll
    for (int i = 0; i < 4; ++i) {
        int m = m0 + ty * 4 + i;
        const float4 zv4 = *reinterpret_cast<const float4*>(z + (size_t)m * Bdim + b0 + tx * 4);
        float4 o4;
        o4.x = acc[i][0] + zv4.x * accA[i][0];
        o4.y = acc[i][1] + zv4.y * accA[i][1];
        o4.z = acc[i][2] + zv4.z * accA[i][2];
        o4.w = acc[i][3] + zv4.w * accA[i][3];
        *reinterpret_cast<float4*>(out + (size_t)m * Bdim + b0 + tx * 4) = o4;
    }
}

// ---------------- launch ----------------
extern "C" void kernel_launch(void* const* d_in, const int* in_sizes, int n_in,
                              void* d_out, int out_size)
{
    const float* z       = (const float*)d_in[0];
    const float* ctx     = (const float*)d_in[1];
    const float* noise   = (const float*)d_in[2];
    const float* conv_w  = (const float*)d_in[3];
    const float* conv_b  = (const float*)d_in[4];
    const float* Dm      = (const float*)d_in[5];
    const float* sigma_g = (const float*)d_in[6];
    const float* temp1   = (const float*)d_in[7];
    const float* W1      = (const float*)d_in[8];
    const float* b1      = (const float*)d_in[9];
    const float* W2      = (const float*)d_in[10];
    const float* b2      = (const float*)d_in[11];
    const float* temp2   = (const float*)d_in[12];
    const float* Amat    = (const float*)d_in[13];
    const float* Wx      = (const float*)d_in[14];
    const float* hmat    = (const float*)d_in[15];
    float* out = (float*)d_out;

    k_zc<<<dim3(Bdim / 256, Ndim), 256>>>(z, noise, Dm, sigma_g);
    k_attn<<<Bdim / K2_WARPS, 256>>>(ctx, z, conv_w, conv_b, temp1, W1, b1, W2, b2, temp2);
    k_mix<<<dim3(Bdim / K3_BT, Mdim / K3_MT), 256>>>(z, Wx, Amat, hmat, out);
}